// round 11
// baseline (speedup 1.0000x reference)
#include <cuda_runtime.h>
#include <cuda_fp16.h>
#include <math.h>
#include <stdint.h>

// Problem constants
#define NIMG   32
#define HH     96
#define WW     96
#define LPIX   (HH*WW)              // 9216
#define MROWS  (NIMG*LPIX)          // 294912
#define NBINS  17
#define REGOUT (4*NBINS)            // 68
#define REGCH  64

// ---------------------------------------------------------------------------
// Scratch device globals
// ---------------------------------------------------------------------------
__device__ __align__(16) __half g_buf1[(size_t)MROWS * 512];  // L1 out [cls h1 | reg h1]
__device__ __align__(16) __half g_buf2[(size_t)MROWS * 256];  // reg h2
__device__ float g_cls[MROWS];                                // cls dot accumulator
// fp16 weights: [cw1(256) | rw1(256) | cw2(256) | rw2(256) | rw3(68)] x 256
__device__ __align__(16) __half g_wh[(size_t)(4 * 256 + 68) * 256];
__device__ float g_b512[512];                                 // concat(cb1, rb1)

// ---------------------------------------------------------------------------
// helpers
// ---------------------------------------------------------------------------
__device__ __forceinline__ uint32_t smem_u32(const void* p) {
    uint32_t a;
    asm("{ .reg .u64 t; cvta.to.shared.u64 t, %1; cvt.u32.u64 %0, t; }" : "=r"(a) : "l"(p));
    return a;
}
#define CP16(dst, gsrc, nbytes) \
    asm volatile("cp.async.cg.shared.global [%0], [%1], 16, %2;" \
                 :: "r"(dst), "l"(gsrc), "r"(nbytes))
#define CP_COMMIT() asm volatile("cp.async.commit_group;" ::: "memory")
#define CP_WAIT(n)  asm volatile("cp.async.wait_group %0;" :: "n"(n) : "memory")

// fp16 MMA m16n8k16, fp32 accumulate
#define MMA16(c, a, b)                                                       \
    asm volatile("mma.sync.aligned.m16n8k16.row.col.f32.f16.f16.f32 "        \
        "{%0,%1,%2,%3}, {%4,%5,%6,%7}, {%8,%9}, {%0,%1,%2,%3};"              \
        : "+f"((c)[0]), "+f"((c)[1]), "+f"((c)[2]), "+f"((c)[3])             \
        : "r"((a)[0]), "r"((a)[1]), "r"((a)[2]), "r"((a)[3]),                \
          "r"((b)[0]), "r"((b)[1]))

#define LDSM4(r0, r1, r2, r3, addr)                                          \
    asm volatile("ldmatrix.sync.aligned.m8n8.x4.shared.b16 {%0,%1,%2,%3}, [%4];" \
        : "=r"(r0), "=r"(r1), "=r"(r2), "=r"(r3) : "r"(addr))

// ====== generic fp16 GEMM (R9 config): BK=64, PADB=144, 256 thr ======
#define PADB 144
#define STAGE_B (128 * PADB)                 // 18432 B per operand per stage
#define NSTAGE 3
#define SMEM_BYTES (NSTAGE * STAGE_B * 2)    // 110592 -> 2 CTAs/SM
#define NKT 4                                // 256 / 64

#define MODE_STD 0   // bias + relu -> fp16 store
#define MODE_P68 1   // bias only -> fp32 store, col<68 guard
#define MODE_DOT 2   // bias + relu, dot with w3, atomicAdd into dotOut

__global__ void __launch_bounds__(256, 2)
gemm_f16(const __half* __restrict__ A, int lda,
         const __half* __restrict__ W,
         const float* __restrict__ bias,
         void* __restrict__ Cout, int ldc, int Nout, int mode,
         const float* __restrict__ w3, float* __restrict__ dotOut)
{
    extern __shared__ __align__(16) char smraw[];
    const uint32_t smA = smem_u32(smraw);
    const uint32_t smB = smA + NSTAGE * STAGE_B;

    const int tid = threadIdx.x;
    const int bm = blockIdx.y * 128;
    const int bn = blockIdx.x * 128;
    const int warp = tid >> 5, lane = tid & 31;
    const int wm = warp & 1, wn = warp >> 1;       // wm: 64-row half, wn: 32-col slice
    const int lq = lane >> 2, lr = lane & 3;

    float acc[4][4][4];
#pragma unroll
    for (int i = 0; i < 4; i++)
#pragma unroll
        for (int j = 0; j < 4; j++)
#pragma unroll
            for (int q = 0; q < 4; q++) acc[i][j][q] = 0.f;

    const int lrow = tid >> 3;          // 0..31
    const int lseg = (tid & 7) * 8;     // halfs: 0,8,...,56 (16B segments)

    const __half* aG = A + (size_t)(bm + lrow) * lda + lseg;
    const __half* bG = W + (size_t)(bn + lrow) * 256 + lseg;

    const uint32_t aFragOff = (uint32_t)((lane & 15) * PADB + ((lane >> 4) & 1) * 16)
                            + (uint32_t)(wm * 64 * PADB);
    const uint32_t bFragOff = (uint32_t)(((lane & 7) + ((lane >> 4) & 1) * 8) * PADB
                            + ((lane >> 3) & 1) * 16)
                            + (uint32_t)(wn * 32 * PADB);

#define ISSUE_TILE(buf, k0)                                                   \
    do {                                                                      \
        uint32_t dA = smA + (buf) * STAGE_B + lrow * PADB + (tid & 7) * 16;   \
        uint32_t dB = smB + (buf) * STAGE_B + lrow * PADB + (tid & 7) * 16;   \
        _Pragma("unroll")                                                     \
        for (int it = 0; it < 4; it++) {                                      \
            CP16(dA + it * 32 * PADB,                                         \
                 __cvta_generic_to_global(aG + (size_t)it * 32 * lda + (k0)), \
                 16);                                                         \
            int brow = bn + lrow + it * 32;                                   \
            CP16(dB + it * 32 * PADB,                                         \
                 __cvta_generic_to_global(bG + (size_t)it * 32 * 256 + (k0)), \
                 (brow < Nout) ? 16 : 0);                                     \
        }                                                                     \
        CP_COMMIT();                                                          \
    } while (0)

    ISSUE_TILE(0, 0);
    ISSUE_TILE(1, 64);

    for (int kt = 0; kt < NKT; kt++) {
        if (kt < NKT - 2) ISSUE_TILE((kt + 2) % NSTAGE, (kt + 2) * 64);
        else              CP_COMMIT();
        CP_WAIT(2);
        __syncthreads();

        const int buf = kt % NSTAGE;
        const uint32_t aBase = smA + (uint32_t)(buf * STAGE_B) + aFragOff;
        const uint32_t bBase = smB + (uint32_t)(buf * STAGE_B) + bFragOff;

#pragma unroll
        for (int kk = 0; kk < 4; kk++) {       // 4 k16 slices per BK64
            uint32_t a[4][4], b[4][2];
#pragma unroll
            for (int i = 0; i < 4; i++)
                LDSM4(a[i][0], a[i][1], a[i][2], a[i][3],
                      aBase + (uint32_t)(i * 16 * PADB + kk * 32));
#pragma unroll
            for (int jp = 0; jp < 2; jp++)
                LDSM4(b[2 * jp][0], b[2 * jp][1], b[2 * jp + 1][0], b[2 * jp + 1][1],
                      bBase + (uint32_t)(jp * 16 * PADB + kk * 32));
#pragma unroll
            for (int i = 0; i < 4; i++)
#pragma unroll
                for (int j = 0; j < 4; j++)
                    MMA16(acc[i][j], a[i], b[j]);
        }
        __syncthreads();
    }
#undef ISSUE_TILE

    // ---------------- Epilogue ----------------
    if (mode == MODE_DOT) {
#pragma unroll
        for (int i = 0; i < 4; i++) {
            int r0 = bm + wm * 64 + i * 16 + lq;
            float s0 = 0.f, s1 = 0.f;
#pragma unroll
            for (int j = 0; j < 4; j++) {
                int col = bn + wn * 32 + j * 8 + 2 * lr;
                float b0 = __ldg(bias + col), b1 = __ldg(bias + col + 1);
                float w0 = __ldg(w3 + col), w1 = __ldg(w3 + col + 1);
                float c0 = fmaxf(acc[i][j][0] + b0, 0.f);
                float c1 = fmaxf(acc[i][j][1] + b1, 0.f);
                float c2 = fmaxf(acc[i][j][2] + b0, 0.f);
                float c3 = fmaxf(acc[i][j][3] + b1, 0.f);
                s0 = fmaf(c0, w0, fmaf(c1, w1, s0));
                s1 = fmaf(c2, w0, fmaf(c3, w1, s1));
            }
#pragma unroll
            for (int o = 1; o < 4; o <<= 1) {
                s0 += __shfl_xor_sync(0xffffffffu, s0, o);
                s1 += __shfl_xor_sync(0xffffffffu, s1, o);
            }
            if (lr == 0) {
                atomicAdd(dotOut + r0, s0);
                atomicAdd(dotOut + r0 + 8, s1);
            }
        }
        return;
    }

    if (mode == MODE_STD) {
        __half* C = (__half*)Cout;
#pragma unroll
        for (int i = 0; i < 4; i++) {
#pragma unroll
            for (int j = 0; j < 4; j++) {
                int row = bm + wm * 64 + i * 16 + lq;
                int col = bn + wn * 32 + j * 8 + 2 * lr;
                float b0 = __ldg(bias + col), b1 = __ldg(bias + col + 1);
                __half2 h01 = __floats2half2_rn(fmaxf(acc[i][j][0] + b0, 0.f),
                                                fmaxf(acc[i][j][1] + b1, 0.f));
                __half2 h23 = __floats2half2_rn(fmaxf(acc[i][j][2] + b0, 0.f),
                                                fmaxf(acc[i][j][3] + b1, 0.f));
                *(__half2*)(C + (size_t)row * ldc + col)       = h01;
                *(__half2*)(C + (size_t)(row + 8) * ldc + col) = h23;
            }
        }
    } else { // MODE_P68, fp32 out
        float* C = (float*)Cout;
#pragma unroll
        for (int i = 0; i < 4; i++) {
#pragma unroll
            for (int j = 0; j < 4; j++) {
                int row = bm + wm * 64 + i * 16 + lq;
                int col = bn + wn * 32 + j * 8 + 2 * lr;
                if (col >= 68) continue;
                float b0 = __ldg(bias + col), b1 = __ldg(bias + col + 1);
                *(float2*)(C + (size_t)row * ldc + col) =
                    make_float2(acc[i][j][0] + b0, acc[i][j][1] + b1);
                *(float2*)(C + (size_t)(row + 8) * ldc + col) =
                    make_float2(acc[i][j][2] + b0, acc[i][j][3] + b1);
            }
        }
    }
}

// ====== L1 GEMM with fused fp32->fp16 A conversion ======
// BK=32 elements, 8 k-tiles. A: LDG fp32 -> cvt -> STS fp16 (2-slot, 1-ahead).
// B: cp.async fp16 (3-slot, 2-ahead). Row pad 80B. 256 thr, 8 warps 64x32.
#define APB 80
#define ASTG_C (128 * APB)                   // 10240 B
#define CVT_SMEM (5 * ASTG_C)                // 2 A slots + 3 B slots = 51200

__global__ void __launch_bounds__(256, 2)
gemm_f16_cvt(const float* __restrict__ X,     // fp32 A [M,256]
             const __half* __restrict__ W,    // fp16 [512,256]
             const float* __restrict__ bias,  // [512]
             __half* __restrict__ C)          // fp16 [M,512]
{
    extern __shared__ __align__(16) char smraw[];
    char* smemc = smraw;
    const uint32_t smA = smem_u32(smraw);
    const uint32_t smB = smA + 2 * ASTG_C;

    const int tid = threadIdx.x;
    const int bm = blockIdx.y * 128;
    const int bn = blockIdx.x * 128;
    const int warp = tid >> 5, lane = tid & 31;
    const int wm = warp & 1, wn = warp >> 1;
    const int lq = lane >> 2, lr = lane & 3;

    float acc[4][4][4];
#pragma unroll
    for (int i = 0; i < 4; i++)
#pragma unroll
        for (int j = 0; j < 4; j++)
#pragma unroll
            for (int q = 0; q < 4; q++) acc[i][j][q] = 0.f;

    // A ldg/sts mapping: thread -> one row, half of 32 fp32 cols
    const int rowl = tid >> 1;            // 0..127
    const int halfs = tid & 1;            // 16-fp32 half
    const float* xrow = X + (size_t)(bm + rowl) * 256 + halfs * 16;
    const uint32_t aStsOff = (uint32_t)(rowl * APB + halfs * 32);

    // B cp.async mapping: 4 threads/row
    const int browt = tid >> 2;           // 0..63
    const int bseg = tid & 3;
    const __half* bG = W + (size_t)(bn + browt) * 256 + bseg * 8;
    const uint32_t bStsOff = (uint32_t)(browt * APB + bseg * 16);

    const uint32_t aFragOff = (uint32_t)((lane & 15) * APB + ((lane >> 4) & 1) * 16)
                            + (uint32_t)(wm * 64 * APB);
    const uint32_t bFragOff = (uint32_t)(((lane & 7) + ((lane >> 4) & 1) * 8) * APB
                            + ((lane >> 3) & 1) * 16)
                            + (uint32_t)(wn * 32 * APB);

    float4 abuf[4];

#define LDG_A(j)                                                              \
    do {                                                                      \
        const float4* s = (const float4*)(xrow + (j) * 32);                   \
        abuf[0] = s[0]; abuf[1] = s[1]; abuf[2] = s[2]; abuf[3] = s[3];       \
    } while (0)

#define STS_A(j)                                                              \
    do {                                                                      \
        union { __half2 h[2]; uint2 u; } p0, p1;                              \
        char* dst = smemc + ((j) & 1) * ASTG_C + aStsOff;                     \
        p0.h[0] = __floats2half2_rn(abuf[0].x, abuf[0].y);                    \
        p0.h[1] = __floats2half2_rn(abuf[0].z, abuf[0].w);                    \
        p1.h[0] = __floats2half2_rn(abuf[1].x, abuf[1].y);                    \
        p1.h[1] = __floats2half2_rn(abuf[1].z, abuf[1].w);                    \
        *(uint4*)dst = make_uint4(p0.u.x, p0.u.y, p1.u.x, p1.u.y);            \
        p0.h[0] = __floats2half2_rn(abuf[2].x, abuf[2].y);                    \
        p0.h[1] = __floats2half2_rn(abuf[2].z, abuf[2].w);                    \
        p1.h[0] = __floats2half2_rn(abuf[3].x, abuf[3].y);                    \
        p1.h[1] = __floats2half2_rn(abuf[3].z, abuf[3].w);                    \
        *(uint4*)(dst + 16) = make_uint4(p0.u.x, p0.u.y, p1.u.x, p1.u.y);     \
    } while (0)

#define ISSUE_B(j)                                                            \
    do {                                                                      \
        uint32_t dB = smB + ((j) % 3) * ASTG_C + bStsOff;                     \
        CP16(dB,                 __cvta_generic_to_global(bG + (j) * 32), 16);\
        CP16(dB + 64 * APB,      __cvta_generic_to_global(bG + (size_t)64 * 256 + (j) * 32), 16); \
        CP_COMMIT();                                                          \
    } while (0)

    // prologue
    LDG_A(0);
    STS_A(0);            // blocking once
    LDG_A(1);            // for iter 0's STS
    ISSUE_B(0);
    ISSUE_B(1);
    __syncthreads();     // A(0) visible

    for (int kt = 0; kt < 8; kt++) {
        if (kt < 6) ISSUE_B(kt + 2);
        else        CP_COMMIT();
        CP_WAIT(2);
        __syncthreads();

        const uint32_t aBase = smA + (uint32_t)((kt & 1) * ASTG_C) + aFragOff;
        const uint32_t bBase = smB + (uint32_t)((kt % 3) * ASTG_C) + bFragOff;

#pragma unroll
        for (int kk = 0; kk < 2; kk++) {
            uint32_t a[4][4], b[4][2];
#pragma unroll
            for (int i = 0; i < 4; i++)
                LDSM4(a[i][0], a[i][1], a[i][2], a[i][3],
                      aBase + (uint32_t)(i * 16 * APB + kk * 32));
#pragma unroll
            for (int jp = 0; jp < 2; jp++)
                LDSM4(b[2 * jp][0], b[2 * jp][1], b[2 * jp + 1][0], b[2 * jp + 1][1],
                      bBase + (uint32_t)(jp * 16 * APB + kk * 32));
#pragma unroll
            for (int i = 0; i < 4; i++)
#pragma unroll
                for (int j = 0; j < 4; j++)
                    MMA16(acc[i][j], a[i], b[j]);
        }

        if (kt < 7) {
            STS_A(kt + 1);               // data LDG'd last iter / prologue
            if (kt < 6) LDG_A(kt + 2);   // for next iter's STS
        }
        __syncthreads();
    }
#undef LDG_A
#undef STS_A
#undef ISSUE_B

    // Epilogue: bias + relu -> fp16, ldc = 512
#pragma unroll
    for (int i = 0; i < 4; i++) {
#pragma unroll
        for (int j = 0; j < 4; j++) {
            int row = bm + wm * 64 + i * 16 + lq;
            int col = bn + wn * 32 + j * 8 + 2 * lr;
            float b0 = __ldg(bias + col), b1 = __ldg(bias + col + 1);
            __half2 h01 = __floats2half2_rn(fmaxf(acc[i][j][0] + b0, 0.f),
                                            fmaxf(acc[i][j][1] + b1, 0.f));
            __half2 h23 = __floats2half2_rn(fmaxf(acc[i][j][2] + b0, 0.f),
                                            fmaxf(acc[i][j][3] + b1, 0.f));
            *(__half2*)(C + (size_t)row * 512 + col)       = h01;
            *(__half2*)(C + (size_t)(row + 8) * 512 + col) = h23;
        }
    }
}

// ---------------------------------------------------------------------------
// prep1: L1 weights (cw1 | rw1) -> fp16 wh_l1   (32768 float4s)
// ---------------------------------------------------------------------------
__global__ void __launch_bounds__(256)
prep1_kernel(const float4* __restrict__ cw1, const float4* __restrict__ rw1,
             __half* __restrict__ wh_l1)
{
    int i = blockIdx.x * blockDim.x + threadIdx.x;
    if (i >= 32768) return;
    float4 v = (i < 16384) ? cw1[i] : rw1[i - 16384];
    union { __half2 h2[2]; uint2 u; } pk;
    pk.h2[0] = __floats2half2_rn(v.x, v.y);
    pk.h2[1] = __floats2half2_rn(v.z, v.w);
    *(uint2*)(wh_l1 + (size_t)i * 4) = pk.u;
}

// ---------------------------------------------------------------------------
// prep2: cw2/rw2/rw3 -> fp16, concat biases, zero cls accumulator
// ---------------------------------------------------------------------------
__global__ void __launch_bounds__(256)
prep2_kernel(const float4* __restrict__ cw2, const float4* __restrict__ rw2,
             const float4* __restrict__ rw3,
             const float4* __restrict__ cb1, const float4* __restrict__ rb1,
             __half* __restrict__ wh_cw2, __half* __restrict__ wh_rw2,
             __half* __restrict__ wh_rw3, float4* __restrict__ b512,
             float4* __restrict__ clszero)
{
    int i = blockIdx.x * blockDim.x + threadIdx.x;
    union { __half2 h2[2]; uint2 u; } pk;
    if (i < 16384) {
        float4 v = cw2[i];
        pk.h2[0] = __floats2half2_rn(v.x, v.y);
        pk.h2[1] = __floats2half2_rn(v.z, v.w);
        *(uint2*)(wh_cw2 + (size_t)i * 4) = pk.u;
    } else if (i < 32768) {
        float4 v = rw2[i - 16384];
        pk.h2[0] = __floats2half2_rn(v.x, v.y);
        pk.h2[1] = __floats2half2_rn(v.z, v.w);
        *(uint2*)(wh_rw2 + (size_t)(i - 16384) * 4) = pk.u;
    } else if (i < 37120) {
        float4 v = rw3[i - 32768];
        pk.h2[0] = __floats2half2_rn(v.x, v.y);
        pk.h2[1] = __floats2half2_rn(v.z, v.w);
        *(uint2*)(wh_rw3 + (size_t)(i - 32768) * 4) = pk.u;
    } else if (i < 37248) {
        int k = i - 37120;
        b512[k] = (k < 64) ? cb1[k] : rb1[k - 64];
    } else if (i < 37248 + 73728) {
        clszero[i - 37248] = make_float4(0.f, 0.f, 0.f, 0.f);
    }
}

// ---------------------------------------------------------------------------
// Head: softmax-17 x4, top4+mean, quality MLP, sigmoid(cls)*q, integral box.
// ---------------------------------------------------------------------------
__global__ void __launch_bounds__(128)
head_kernel(const float* __restrict__ reg, const float* __restrict__ clsl,
            const float* __restrict__ cb3,
            const float* __restrict__ qw1, const float* __restrict__ qb1,
            const float* __restrict__ qw2, const float* __restrict__ qb2,
            float* __restrict__ outCls, float* __restrict__ outBox, int M)
{
    __shared__ float sw1[REGCH * 20];
    __shared__ float sb1[REGCH];
    __shared__ float sw2[REGCH];
    __shared__ float sb2;
    for (int i = threadIdx.x; i < REGCH * 20; i += blockDim.x) sw1[i] = qw1[i];
    for (int i = threadIdx.x; i < REGCH; i += blockDim.x) {
        sb1[i] = qb1[i];
        sw2[i] = qw2[i];
    }
    if (threadIdx.x == 0) sb2 = qb2[0];
    __syncthreads();

    int p = blockIdx.x * blockDim.x + threadIdx.x;
    if (p >= M) return;

    const float* rp = reg + (size_t)p * REGOUT;
    float stat[20], box[4];
#pragma unroll
    for (int s = 0; s < 4; s++) {
        float v[NBINS];
        float mx = -1e30f;
#pragma unroll
        for (int i = 0; i < NBINS; i++) { v[i] = rp[s * NBINS + i]; mx = fmaxf(mx, v[i]); }
        float sum = 0.f;
#pragma unroll
        for (int i = 0; i < NBINS; i++) { v[i] = expf(v[i] - mx); sum += v[i]; }
        float inv = 1.f / sum, integ = 0.f;
#pragma unroll
        for (int i = 0; i < NBINS; i++) { v[i] *= inv; integ += v[i] * (float)i; }
        box[s] = integ * (1.f / 16.f);
        float mean4 = 0.f;
        for (int k = 0; k < 4; k++) {
            float best = -1.f;
            int bi = 0;
#pragma unroll
            for (int i = 0; i < NBINS; i++)
                if (v[i] > best) { best = v[i]; bi = i; }
            stat[s * 5 + k] = best;
            mean4 += best;
            v[bi] = -2.f;
        }
        stat[s * 5 + 4] = mean4 * 0.25f;
    }
    float q = sb2;
    for (int o = 0; o < REGCH; o++) {
        float h = sb1[o];
#pragma unroll
        for (int c = 0; c < 20; c++) h = fmaf(sw1[o * 20 + c], stat[c], h);
        q = fmaf(sw2[o], fmaxf(h, 0.f), q);
    }
    q = 1.f / (1.f + expf(-q));
    float cl = 1.f / (1.f + expf(-(clsl[p] + __ldg(cb3))));
    outCls[p] = cl * q;
    *(float4*)&outBox[(size_t)p * 4] = make_float4(box[0], box[1], box[2], box[3]);
}

// ---------------------------------------------------------------------------
// Launcher
// ---------------------------------------------------------------------------
extern "C" void kernel_launch(void* const* d_in, const int* in_sizes, int n_in,
                              void* d_out, int out_size)
{
    const float* x   = (const float*)d_in[0];
    const float* cw1 = (const float*)d_in[1];
    const float* cb1 = (const float*)d_in[2];
    const float* cw2 = (const float*)d_in[3];
    const float* cb2 = (const float*)d_in[4];
    const float* cw3 = (const float*)d_in[5];
    const float* cb3 = (const float*)d_in[6];
    const float* rw1 = (const float*)d_in[7];
    const float* rb1 = (const float*)d_in[8];
    const float* rw2 = (const float*)d_in[9];
    const float* rb2 = (const float*)d_in[10];
    const float* rw3 = (const float*)d_in[11];
    const float* rb3 = (const float*)d_in[12];
    const float* qw1 = (const float*)d_in[13];
    const float* qb1 = (const float*)d_in[14];
    const float* qw2 = (const float*)d_in[15];
    const float* qb2 = (const float*)d_in[16];

    float* out = (float*)d_out;
    float* outCls = out;
    float* outBox = out + (size_t)MROWS;
    float* outReg = out + (size_t)MROWS * 5;

    __half *buf1, *buf2, *wh;
    float *clsbuf, *b512;
    cudaGetSymbolAddress((void**)&buf1, g_buf1);
    cudaGetSymbolAddress((void**)&buf2, g_buf2);
    cudaGetSymbolAddress((void**)&clsbuf, g_cls);
    cudaGetSymbolAddress((void**)&wh, g_wh);
    cudaGetSymbolAddress((void**)&b512, g_b512);

    __half* wh_l1  = wh;                          // cw1 rows 0..255, rw1 rows 256..511
    __half* wh_cw2 = wh + (size_t)512 * 256;
    __half* wh_rw2 = wh + (size_t)768 * 256;
    __half* wh_rw3 = wh + (size_t)1024 * 256;

    cudaFuncSetAttribute(gemm_f16, cudaFuncAttributeMaxDynamicSharedMemorySize, SMEM_BYTES);
    cudaFuncSetAttribute(gemm_f16_cvt, cudaFuncAttributeMaxDynamicSharedMemorySize, CVT_SMEM);

    // prep
    prep1_kernel<<<128, 256>>>((const float4*)cw1, (const float4*)rw1, wh_l1);
    prep2_kernel<<<434, 256>>>((const float4*)cw2, (const float4*)rw2, (const float4*)rw3,
                               (const float4*)cb1, (const float4*)rb1,
                               wh_cw2, wh_rw2, wh_rw3,
                               (float4*)b512, (float4*)clsbuf);

    const int GY = MROWS / 128;  // 2304

    // Fused layer-1 with in-kernel fp32->fp16 conversion of x
    gemm_f16_cvt<<<dim3(4, GY), 256, CVT_SMEM>>>(x, wh_l1, b512, buf1);
    // reg layer-2
    gemm_f16<<<dim3(2, GY), 256, SMEM_BYTES>>>(buf1 + 256, 512, wh_rw2, rb2,
                                               buf2, 256, 256, MODE_STD, nullptr, nullptr);
    // reg layer-3 (68 outputs, fp32) -> reg_pred output
    gemm_f16<<<dim3(1, GY), 256, SMEM_BYTES>>>(buf2, 256, wh_rw3, rb3,
                                               outReg, 68, 68, MODE_P68, nullptr, nullptr);
    // cls layer-2 + fused dot with cw3 -> clsbuf
    gemm_f16<<<dim3(2, GY), 256, SMEM_BYTES>>>(buf1, 512, wh_cw2, cb2,
                                               nullptr, 0, 256, MODE_DOT, cw3, clsbuf);
    // Fused head
    head_kernel<<<(MROWS + 127) / 128, 128>>>(outReg, clsbuf, cb3, qw1, qb1, qw2, qb2,
                                              outCls, outBox, MROWS);
}

// round 12
// speedup vs baseline: 1.0819x; 1.0819x over previous
#include <cuda_runtime.h>
#include <cuda_fp16.h>
#include <math.h>
#include <stdint.h>

// Problem constants
#define NIMG   32
#define HH     96
#define WW     96
#define LPIX   (HH*WW)              // 9216
#define MROWS  (NIMG*LPIX)          // 294912
#define NBINS  17
#define REGOUT (4*NBINS)            // 68
#define REGCH  64

// ---------------------------------------------------------------------------
// Scratch device globals (fp16 activations/weights)
// ---------------------------------------------------------------------------
__device__ __align__(16) __half g_xh[(size_t)MROWS * 256];    // fp16 x
__device__ __align__(16) __half g_buf1[(size_t)MROWS * 512];  // L1 out [cls h1 | reg h1]
__device__ __align__(16) __half g_buf2[(size_t)MROWS * 256];  // reg h2
__device__ float g_cls[MROWS];                                // cls dot accumulator
// fp16 weights: [cw1(256) | rw1(256) | cw2(256) | rw2(256) | rw3(68)] x 256
__device__ __align__(16) __half g_wh[(size_t)(4 * 256 + 68) * 256];
__device__ float g_b512[512];                                 // concat(cb1, rb1)

// ---------------------------------------------------------------------------
// helpers
// ---------------------------------------------------------------------------
__device__ __forceinline__ uint32_t smem_u32(const void* p) {
    uint32_t a;
    asm("{ .reg .u64 t; cvta.to.shared.u64 t, %1; cvt.u32.u64 %0, t; }" : "=r"(a) : "l"(p));
    return a;
}
#define CP16(dst, gsrc, nbytes) \
    asm volatile("cp.async.cg.shared.global [%0], [%1], 16, %2;" \
                 :: "r"(dst), "l"(gsrc), "r"(nbytes))
#define CP_COMMIT() asm volatile("cp.async.commit_group;" ::: "memory")
#define CP_WAIT(n)  asm volatile("cp.async.wait_group %0;" :: "n"(n) : "memory")

// fp16 MMA m16n8k16, fp32 accumulate
#define MMA16(c, a, b)                                                       \
    asm volatile("mma.sync.aligned.m16n8k16.row.col.f32.f16.f16.f32 "        \
        "{%0,%1,%2,%3}, {%4,%5,%6,%7}, {%8,%9}, {%0,%1,%2,%3};"              \
        : "+f"((c)[0]), "+f"((c)[1]), "+f"((c)[2]), "+f"((c)[3])             \
        : "r"((a)[0]), "r"((a)[1]), "r"((a)[2]), "r"((a)[3]),                \
          "r"((b)[0]), "r"((b)[1]))

#define LDSM4(r0, r1, r2, r3, addr)                                          \
    asm volatile("ldmatrix.sync.aligned.m8n8.x4.shared.b16 {%0,%1,%2,%3}, [%4];" \
        : "=r"(r0), "=r"(r1), "=r"(r2), "=r"(r3) : "r"(addr))

// BK = 64 fp16 columns per k-tile; row stride 144 B (128 data + 16 pad)
#define PADB 144
#define STAGE_B (128 * PADB)                 // 18432 B per operand per stage
#define NSTAGE 3
#define SMEM_BYTES (NSTAGE * STAGE_B * 2)    // 110592 -> 2 CTAs/SM
#define NKT 4                                // 256 / 64

#define MODE_STD 0   // bias + relu -> fp16 store
#define MODE_DOT 2   // bias + relu, dot with w3, atomicAdd into dotOut

// ===========================================================================
// generic fp16 mma GEMM (R9 config — unchanged): CTA 128x128, 256 thr,
// 8 warps (2x4) of 64x32 tiles, BK=64, 3-stage cp.async.
// ===========================================================================
__global__ void __launch_bounds__(256, 2)
gemm_f16(const __half* __restrict__ A, int lda,
         const __half* __restrict__ W,
         const float* __restrict__ bias,
         void* __restrict__ Cout, int ldc, int Nout, int mode,
         const float* __restrict__ w3, float* __restrict__ dotOut)
{
    extern __shared__ __align__(16) char smraw[];
    const uint32_t smA = smem_u32(smraw);
    const uint32_t smB = smA + NSTAGE * STAGE_B;

    const int tid = threadIdx.x;
    const int bm = blockIdx.y * 128;
    const int bn = blockIdx.x * 128;
    const int warp = tid >> 5, lane = tid & 31;
    const int wm = warp & 1, wn = warp >> 1;
    const int lq = lane >> 2, lr = lane & 3;

    float acc[4][4][4];
#pragma unroll
    for (int i = 0; i < 4; i++)
#pragma unroll
        for (int j = 0; j < 4; j++)
#pragma unroll
            for (int q = 0; q < 4; q++) acc[i][j][q] = 0.f;

    const int lrow = tid >> 3;          // 0..31
    const int lseg = (tid & 7) * 8;     // halfs: 0,8,...,56

    const __half* aG = A + (size_t)(bm + lrow) * lda + lseg;
    const __half* bG = W + (size_t)(bn + lrow) * 256 + lseg;

    const uint32_t aFragOff = (uint32_t)((lane & 15) * PADB + ((lane >> 4) & 1) * 16)
                            + (uint32_t)(wm * 64 * PADB);
    const uint32_t bFragOff = (uint32_t)(((lane & 7) + ((lane >> 4) & 1) * 8) * PADB
                            + ((lane >> 3) & 1) * 16)
                            + (uint32_t)(wn * 32 * PADB);

#define ISSUE_TILE(buf, k0)                                                   \
    do {                                                                      \
        uint32_t dA = smA + (buf) * STAGE_B + lrow * PADB + (tid & 7) * 16;   \
        uint32_t dB = smB + (buf) * STAGE_B + lrow * PADB + (tid & 7) * 16;   \
        _Pragma("unroll")                                                     \
        for (int it = 0; it < 4; it++) {                                      \
            CP16(dA + it * 32 * PADB,                                         \
                 __cvta_generic_to_global(aG + (size_t)it * 32 * lda + (k0)), \
                 16);                                                         \
            int brow = bn + lrow + it * 32;                                   \
            CP16(dB + it * 32 * PADB,                                         \
                 __cvta_generic_to_global(bG + (size_t)it * 32 * 256 + (k0)), \
                 (brow < Nout) ? 16 : 0);                                     \
        }                                                                     \
        CP_COMMIT();                                                          \
    } while (0)

    ISSUE_TILE(0, 0);
    ISSUE_TILE(1, 64);

    for (int kt = 0; kt < NKT; kt++) {
        if (kt < NKT - 2) ISSUE_TILE((kt + 2) % NSTAGE, (kt + 2) * 64);
        else              CP_COMMIT();
        CP_WAIT(2);
        __syncthreads();

        const int buf = kt % NSTAGE;
        const uint32_t aBase = smA + (uint32_t)(buf * STAGE_B) + aFragOff;
        const uint32_t bBase = smB + (uint32_t)(buf * STAGE_B) + bFragOff;

#pragma unroll
        for (int kk = 0; kk < 4; kk++) {
            uint32_t a[4][4], b[4][2];
#pragma unroll
            for (int i = 0; i < 4; i++)
                LDSM4(a[i][0], a[i][1], a[i][2], a[i][3],
                      aBase + (uint32_t)(i * 16 * PADB + kk * 32));
#pragma unroll
            for (int jp = 0; jp < 2; jp++)
                LDSM4(b[2 * jp][0], b[2 * jp][1], b[2 * jp + 1][0], b[2 * jp + 1][1],
                      bBase + (uint32_t)(jp * 16 * PADB + kk * 32));
#pragma unroll
            for (int i = 0; i < 4; i++)
#pragma unroll
                for (int j = 0; j < 4; j++)
                    MMA16(acc[i][j], a[i], b[j]);
        }
        __syncthreads();
    }
#undef ISSUE_TILE

    // ---------------- Epilogue ----------------
    if (mode == MODE_DOT) {
#pragma unroll
        for (int i = 0; i < 4; i++) {
            int r0 = bm + wm * 64 + i * 16 + lq;
            float s0 = 0.f, s1 = 0.f;
#pragma unroll
            for (int j = 0; j < 4; j++) {
                int col = bn + wn * 32 + j * 8 + 2 * lr;
                float b0 = __ldg(bias + col), b1 = __ldg(bias + col + 1);
                float w0 = __ldg(w3 + col), w1 = __ldg(w3 + col + 1);
                float c0 = fmaxf(acc[i][j][0] + b0, 0.f);
                float c1 = fmaxf(acc[i][j][1] + b1, 0.f);
                float c2 = fmaxf(acc[i][j][2] + b0, 0.f);
                float c3 = fmaxf(acc[i][j][3] + b1, 0.f);
                s0 = fmaf(c0, w0, fmaf(c1, w1, s0));
                s1 = fmaf(c2, w0, fmaf(c3, w1, s1));
            }
#pragma unroll
            for (int o = 1; o < 4; o <<= 1) {
                s0 += __shfl_xor_sync(0xffffffffu, s0, o);
                s1 += __shfl_xor_sync(0xffffffffu, s1, o);
            }
            if (lr == 0) {
                atomicAdd(dotOut + r0, s0);
                atomicAdd(dotOut + r0 + 8, s1);
            }
        }
        return;
    }

    // MODE_STD: bias + relu -> fp16
    {
        __half* C = (__half*)Cout;
#pragma unroll
        for (int i = 0; i < 4; i++) {
#pragma unroll
            for (int j = 0; j < 4; j++) {
                int row = bm + wm * 64 + i * 16 + lq;
                int col = bn + wn * 32 + j * 8 + 2 * lr;
                float b0 = __ldg(bias + col), b1 = __ldg(bias + col + 1);
                __half2 h01 = __floats2half2_rn(fmaxf(acc[i][j][0] + b0, 0.f),
                                                fmaxf(acc[i][j][1] + b1, 0.f));
                __half2 h23 = __floats2half2_rn(fmaxf(acc[i][j][2] + b0, 0.f),
                                                fmaxf(acc[i][j][3] + b1, 0.f));
                *(__half2*)(C + (size_t)row * ldc + col)       = h01;
                *(__half2*)(C + (size_t)(row + 8) * ldc + col) = h23;
            }
        }
    }
}

// ===========================================================================
// reg layer-3 GEMM (Nout=68) with FUSED HEAD epilogue.
// Same mainloop; after MMAs: store reg_pred to gmem + stage rows in smem,
// then threads 0..127 each run the per-pixel head for one row.
// grid = (1, M/128).
// ===========================================================================
#define STG_STRIDE 72   // floats per staged row (68 + pad, even for float2)

__global__ void __launch_bounds__(256, 2)
gemm_l3_head(const __half* __restrict__ A,        // buf2 [M,256]
             const __half* __restrict__ W,        // rw3 fp16 [68,256]
             const float* __restrict__ bias,      // rb3 [68]
             float* __restrict__ outReg,          // [M,68]
             const float* __restrict__ clsl,      // cls logit accumulator [M]
             const float* __restrict__ cb3,       // [1]
             const float* __restrict__ qw1, const float* __restrict__ qb1,
             const float* __restrict__ qw2, const float* __restrict__ qb2,
             float* __restrict__ outCls,          // [M]
             float* __restrict__ outBox)          // [M,4]
{
    extern __shared__ __align__(16) char smraw[];
    const uint32_t smA = smem_u32(smraw);
    const uint32_t smB = smA + NSTAGE * STAGE_B;

    const int tid = threadIdx.x;
    const int bm = blockIdx.y * 128;
    const int warp = tid >> 5, lane = tid & 31;
    const int wm = warp & 1, wn = warp >> 1;
    const int lq = lane >> 2, lr = lane & 3;

    float acc[4][4][4];
#pragma unroll
    for (int i = 0; i < 4; i++)
#pragma unroll
        for (int j = 0; j < 4; j++)
#pragma unroll
            for (int q = 0; q < 4; q++) acc[i][j][q] = 0.f;

    const int lrow = tid >> 3;
    const int lseg = (tid & 7) * 8;

    const __half* aG = A + (size_t)(bm + lrow) * 256 + lseg;
    const __half* bG = W + (size_t)lrow * 256 + lseg;

    const uint32_t aFragOff = (uint32_t)((lane & 15) * PADB + ((lane >> 4) & 1) * 16)
                            + (uint32_t)(wm * 64 * PADB);
    const uint32_t bFragOff = (uint32_t)(((lane & 7) + ((lane >> 4) & 1) * 8) * PADB
                            + ((lane >> 3) & 1) * 16)
                            + (uint32_t)(wn * 32 * PADB);

#define ISSUE_TILE(buf, k0)                                                   \
    do {                                                                      \
        uint32_t dA = smA + (buf) * STAGE_B + lrow * PADB + (tid & 7) * 16;   \
        uint32_t dB = smB + (buf) * STAGE_B + lrow * PADB + (tid & 7) * 16;   \
        _Pragma("unroll")                                                     \
        for (int it = 0; it < 4; it++) {                                      \
            CP16(dA + it * 32 * PADB,                                         \
                 __cvta_generic_to_global(aG + (size_t)it * 32 * 256 + (k0)), \
                 16);                                                         \
            int brow = lrow + it * 32;                                        \
            CP16(dB + it * 32 * PADB,                                         \
                 __cvta_generic_to_global(bG + (size_t)it * 32 * 256 + (k0)), \
                 (brow < 68) ? 16 : 0);                                       \
        }                                                                     \
        CP_COMMIT();                                                          \
    } while (0)

    ISSUE_TILE(0, 0);
    ISSUE_TILE(1, 64);

    for (int kt = 0; kt < NKT; kt++) {
        if (kt < NKT - 2) ISSUE_TILE((kt + 2) % NSTAGE, (kt + 2) * 64);
        else              CP_COMMIT();
        CP_WAIT(2);
        __syncthreads();

        const int buf = kt % NSTAGE;
        const uint32_t aBase = smA + (uint32_t)(buf * STAGE_B) + aFragOff;
        const uint32_t bBase = smB + (uint32_t)(buf * STAGE_B) + bFragOff;

#pragma unroll
        for (int kk = 0; kk < 4; kk++) {
            uint32_t a[4][4], b[4][2];
#pragma unroll
            for (int i = 0; i < 4; i++)
                LDSM4(a[i][0], a[i][1], a[i][2], a[i][3],
                      aBase + (uint32_t)(i * 16 * PADB + kk * 32));
#pragma unroll
            for (int jp = 0; jp < 2; jp++)
                LDSM4(b[2 * jp][0], b[2 * jp][1], b[2 * jp + 1][0], b[2 * jp + 1][1],
                      bBase + (uint32_t)(jp * 16 * PADB + kk * 32));
#pragma unroll
            for (int i = 0; i < 4; i++)
#pragma unroll
                for (int j = 0; j < 4; j++)
                    MMA16(acc[i][j], a[i], b[j]);
        }
        __syncthreads();
    }
#undef ISSUE_TILE

    // ---- Epilogue 1: write reg_pred to gmem + stage rows into smem ----
    float* stage = (float*)smraw;                  // 128 x STG_STRIDE fp32
    float* swq   = (float*)(smraw + 128 * STG_STRIDE * 4);  // quality weights
    // layout: sw1[1280] | sb1[64] | sw2[64] | sb2[1]
#pragma unroll
    for (int i = 0; i < 4; i++) {
#pragma unroll
        for (int j = 0; j < 4; j++) {
            int rowl = wm * 64 + i * 16 + lq;
            int col = wn * 32 + j * 8 + 2 * lr;
            if (col >= 68) continue;
            float b0 = __ldg(bias + col), b1 = __ldg(bias + col + 1);
            float2 v0 = make_float2(acc[i][j][0] + b0, acc[i][j][1] + b1);
            float2 v1 = make_float2(acc[i][j][2] + b0, acc[i][j][3] + b1);
            *(float2*)(outReg + (size_t)(bm + rowl) * 68 + col)     = v0;
            *(float2*)(outReg + (size_t)(bm + rowl + 8) * 68 + col) = v1;
            *(float2*)(stage + rowl * STG_STRIDE + col)             = v0;
            *(float2*)(stage + (rowl + 8) * STG_STRIDE + col)       = v1;
        }
    }
    // load quality-MLP weights (after mainloop smem is free above stage area)
    for (int i = tid; i < REGCH * 20; i += 256) swq[i] = __ldg(qw1 + i);
    for (int i = tid; i < REGCH; i += 256) {
        swq[1280 + i] = __ldg(qb1 + i);
        swq[1344 + i] = __ldg(qw2 + i);
    }
    if (tid == 0) swq[1408] = __ldg(qb2);
    __syncthreads();

    // ---- Epilogue 2: per-row head (threads 0..127) ----
    if (tid < 128) {
        const int p = bm + tid;
        const float* rp = stage + tid * STG_STRIDE;
        float stat[20], box[4];
#pragma unroll
        for (int s = 0; s < 4; s++) {
            float v[NBINS];
            float mx = -1e30f;
#pragma unroll
            for (int i = 0; i < NBINS; i++) { v[i] = rp[s * NBINS + i]; mx = fmaxf(mx, v[i]); }
            float sum = 0.f;
#pragma unroll
            for (int i = 0; i < NBINS; i++) { v[i] = expf(v[i] - mx); sum += v[i]; }
            float inv = 1.f / sum, integ = 0.f;
#pragma unroll
            for (int i = 0; i < NBINS; i++) { v[i] *= inv; integ += v[i] * (float)i; }
            box[s] = integ * (1.f / 16.f);
            float mean4 = 0.f;
            for (int k = 0; k < 4; k++) {
                float best = -1.f;
                int bi = 0;
#pragma unroll
                for (int i = 0; i < NBINS; i++)
                    if (v[i] > best) { best = v[i]; bi = i; }
                stat[s * 5 + k] = best;
                mean4 += best;
                v[bi] = -2.f;
            }
            stat[s * 5 + 4] = mean4 * 0.25f;
        }
        float q = swq[1408];
        for (int o = 0; o < REGCH; o++) {
            float h = swq[1280 + o];
#pragma unroll
            for (int c = 0; c < 20; c++) h = fmaf(swq[o * 20 + c], stat[c], h);
            q = fmaf(swq[1344 + o], fmaxf(h, 0.f), q);
        }
        q = 1.f / (1.f + expf(-q));
        float cl = 1.f / (1.f + expf(-(clsl[p] + __ldg(cb3))));
        outCls[p] = cl * q;
        *(float4*)&outBox[(size_t)p * 4] = make_float4(box[0], box[1], box[2], box[3]);
    }
}

// ---------------------------------------------------------------------------
// x -> fp16 conversion (float4 -> 4 halfs)
// ---------------------------------------------------------------------------
__global__ void __launch_bounds__(256)
xcvt_kernel(const float4* __restrict__ in, __half* __restrict__ out, long n4)
{
    long i = (long)blockIdx.x * blockDim.x + threadIdx.x;
    if (i >= n4) return;
    float4 v = in[i];
    union { __half2 h2[2]; uint2 u; } pk;
    pk.h2[0] = __floats2half2_rn(v.x, v.y);
    pk.h2[1] = __floats2half2_rn(v.z, v.w);
    *(uint2*)(out + i * 4) = pk.u;
}

// ---------------------------------------------------------------------------
// prep1: L1 weights (cw1 | rw1) -> fp16 wh_l1   (32768 float4s)
// ---------------------------------------------------------------------------
__global__ void __launch_bounds__(256)
prep1_kernel(const float4* __restrict__ cw1, const float4* __restrict__ rw1,
             __half* __restrict__ wh_l1)
{
    int i = blockIdx.x * blockDim.x + threadIdx.x;
    if (i >= 32768) return;
    float4 v = (i < 16384) ? cw1[i] : rw1[i - 16384];
    union { __half2 h2[2]; uint2 u; } pk;
    pk.h2[0] = __floats2half2_rn(v.x, v.y);
    pk.h2[1] = __floats2half2_rn(v.z, v.w);
    *(uint2*)(wh_l1 + (size_t)i * 4) = pk.u;
}

// ---------------------------------------------------------------------------
// prep2: cw2/rw2/rw3 -> fp16, concat biases, zero cls accumulator
// ---------------------------------------------------------------------------
__global__ void __launch_bounds__(256)
prep2_kernel(const float4* __restrict__ cw2, const float4* __restrict__ rw2,
             const float4* __restrict__ rw3,
             const float4* __restrict__ cb1, const float4* __restrict__ rb1,
             __half* __restrict__ wh_cw2, __half* __restrict__ wh_rw2,
             __half* __restrict__ wh_rw3, float4* __restrict__ b512,
             float4* __restrict__ clszero)
{
    int i = blockIdx.x * blockDim.x + threadIdx.x;
    union { __half2 h2[2]; uint2 u; } pk;
    if (i < 16384) {
        float4 v = cw2[i];
        pk.h2[0] = __floats2half2_rn(v.x, v.y);
        pk.h2[1] = __floats2half2_rn(v.z, v.w);
        *(uint2*)(wh_cw2 + (size_t)i * 4) = pk.u;
    } else if (i < 32768) {
        float4 v = rw2[i - 16384];
        pk.h2[0] = __floats2half2_rn(v.x, v.y);
        pk.h2[1] = __floats2half2_rn(v.z, v.w);
        *(uint2*)(wh_rw2 + (size_t)(i - 16384) * 4) = pk.u;
    } else if (i < 37120) {
        float4 v = rw3[i - 32768];
        pk.h2[0] = __floats2half2_rn(v.x, v.y);
        pk.h2[1] = __floats2half2_rn(v.z, v.w);
        *(uint2*)(wh_rw3 + (size_t)(i - 32768) * 4) = pk.u;
    } else if (i < 37248) {
        int k = i - 37120;
        b512[k] = (k < 64) ? cb1[k] : rb1[k - 64];
    } else if (i < 37248 + 73728) {
        clszero[i - 37248] = make_float4(0.f, 0.f, 0.f, 0.f);
    }
}

// ---------------------------------------------------------------------------
// Launcher
// ---------------------------------------------------------------------------
extern "C" void kernel_launch(void* const* d_in, const int* in_sizes, int n_in,
                              void* d_out, int out_size)
{
    const float* x   = (const float*)d_in[0];
    const float* cw1 = (const float*)d_in[1];
    const float* cb1 = (const float*)d_in[2];
    const float* cw2 = (const float*)d_in[3];
    const float* cb2 = (const float*)d_in[4];
    const float* cw3 = (const float*)d_in[5];
    const float* cb3 = (const float*)d_in[6];
    const float* rw1 = (const float*)d_in[7];
    const float* rb1 = (const float*)d_in[8];
    const float* rw2 = (const float*)d_in[9];
    const float* rb2 = (const float*)d_in[10];
    const float* rw3 = (const float*)d_in[11];
    const float* rb3 = (const float*)d_in[12];
    const float* qw1 = (const float*)d_in[13];
    const float* qb1 = (const float*)d_in[14];
    const float* qw2 = (const float*)d_in[15];
    const float* qb2 = (const float*)d_in[16];

    float* out = (float*)d_out;
    float* outCls = out;
    float* outBox = out + (size_t)MROWS;
    float* outReg = out + (size_t)MROWS * 5;

    __half *xh, *buf1, *buf2, *wh;
    float *clsbuf, *b512;
    cudaGetSymbolAddress((void**)&xh, g_xh);
    cudaGetSymbolAddress((void**)&buf1, g_buf1);
    cudaGetSymbolAddress((void**)&buf2, g_buf2);
    cudaGetSymbolAddress((void**)&clsbuf, g_cls);
    cudaGetSymbolAddress((void**)&wh, g_wh);
    cudaGetSymbolAddress((void**)&b512, g_b512);

    __half* wh_l1  = wh;                          // cw1 rows 0..255, rw1 rows 256..511
    __half* wh_cw2 = wh + (size_t)512 * 256;
    __half* wh_rw2 = wh + (size_t)768 * 256;
    __half* wh_rw3 = wh + (size_t)1024 * 256;

    cudaFuncSetAttribute(gemm_f16, cudaFuncAttributeMaxDynamicSharedMemorySize, SMEM_BYTES);
    cudaFuncSetAttribute(gemm_l3_head, cudaFuncAttributeMaxDynamicSharedMemorySize, SMEM_BYTES);

    // prep
    prep1_kernel<<<128, 256>>>((const float4*)cw1, (const float4*)rw1, wh_l1);
    prep2_kernel<<<434, 256>>>((const float4*)cw2, (const float4*)rw2, (const float4*)rw3,
                               (const float4*)cb1, (const float4*)rb1,
                               wh_cw2, wh_rw2, wh_rw3,
                               (float4*)b512, (float4*)clsbuf);
    xcvt_kernel<<<(MROWS * 64 + 255) / 256, 256>>>((const float4*)x, xh, (long)MROWS * 64);

    const int GY = MROWS / 128;  // 2304

    // Fused layer-1: x(fp16) -> [cls h1 | reg h1] fp16
    gemm_f16<<<dim3(4, GY), 256, SMEM_BYTES>>>(xh, 256, wh_l1, b512,
                                               buf1, 512, 512, MODE_STD, nullptr, nullptr);
    // cls layer-2 + fused dot with cw3 -> clsbuf   (must precede L3+head)
    gemm_f16<<<dim3(2, GY), 256, SMEM_BYTES>>>(buf1, 512, wh_cw2, cb2,
                                               nullptr, 0, 256, MODE_DOT, cw3, clsbuf);
    // reg layer-2
    gemm_f16<<<dim3(2, GY), 256, SMEM_BYTES>>>(buf1 + 256, 512, wh_rw2, rb2,
                                               buf2, 256, 256, MODE_STD, nullptr, nullptr);
    // reg layer-3 + fused head -> outReg, outCls, outBox
    gemm_l3_head<<<dim3(1, GY), 256, SMEM_BYTES>>>(buf2, wh_rw3, rb3, outReg,
                                                   clsbuf, cb3, qw1, qb1, qw2, qb2,
                                                   outCls, outBox);
}